// round 13
// baseline (speedup 1.0000x reference)
#include <cuda_runtime.h>
#include <cstdint>

// Problem constants (fixed by the reference)
#define N_NODES 50000
#define N_EDGES 600000
#define C 128
#define H 256
#define EPS_GEN 1e-7f
#define EPS_BN  1e-5f

// ---------------- scratch (device globals; no allocation allowed) ----------
__device__ float g_h  [N_NODES * C];   // relu(BN(x))
__device__ float g_min[N_NODES * C];   // mlp input = agg + h
__device__ float g_y0 [N_NODES * H];
__device__ float g_y1 [N_NODES * H];
__device__ float g_sum[H];             // zero-init; self-zeroed by finalize
__device__ float g_sumsq[H];
__device__ float g_scale[H];
__device__ float g_shift[H];
__device__ unsigned g_w1t[C * H];      // tf32-rounded W1
__device__ unsigned g_w2t[H * H];      // tf32-rounded W2
__device__ unsigned g_wct[384 * 128];  // tf32-rounded [W3@We ; We]
__device__ float g_bc [128];           // b3@We + be

// CSR-by-dst scratch
#define SCAN_B 512
#define NSCAN ((N_NODES + SCAN_B - 1) / SCAN_B)
__device__ int g_cnt [N_NODES];        // zero-init; self-zeroed by scan_final
__device__ int g_cur [N_NODES];
__device__ int g_off [N_NODES + 1];
__device__ int g_bsum[NSCAN];
__device__ int g_srcs[N_EDGES];

__device__ __forceinline__ unsigned f2tf32(float v) {
    unsigned u;
    asm("cvt.rna.tf32.f32 %0, %1;" : "=r"(u) : "f"(v));
    return u;
}

// ---------------- BN utility kernels ---------------------------------------
// Column stats: blockDim.x == Ccols. Requires g_sum/g_sumsq zero on entry
// (zero-init at load; re-zeroed by finalize_stats after each consume).
__global__ void colstats(const float* __restrict__ A, int rows, int Ccols) {
    int c = threadIdx.x;
    float s = 0.f, sq = 0.f;
    for (int r = blockIdx.x; r < rows; r += gridDim.x) {
        float v = A[(size_t)r * Ccols + c];
        s += v;
        sq += v * v;
    }
    atomicAdd(&g_sum[c], s);
    atomicAdd(&g_sumsq[c], sq);
}

__global__ void finalize_stats(int Ccols, int rows,
                               const float* __restrict__ g,
                               const float* __restrict__ b) {
    int c = threadIdx.x;
    if (c < Ccols) {
        float mean = g_sum[c] / rows;
        float var  = g_sumsq[c] / rows - mean * mean;
        float rs   = rsqrtf(var + EPS_BN);
        float sc   = rs * g[c];
        g_scale[c] = sc;
        g_shift[c] = b[c] - mean * sc;
        g_sum[c]   = 0.f;   // self-zero for next consumer / next replay
        g_sumsq[c] = 0.f;
    }
}

// h = relu(x*scale + shift), float4-vectorized
__global__ void bn_relu4(const float* __restrict__ A, float* __restrict__ O,
                         int total4, int cmask4) {
    int i = blockIdx.x * blockDim.x + threadIdx.x;
    int stride = gridDim.x * blockDim.x;
    for (; i < total4; i += stride) {
        int c4 = (i & cmask4) * 4;
        float4 v  = ((const float4*)A)[i];
        float4 sc = *(const float4*)&g_scale[c4];
        float4 sh = *(const float4*)&g_shift[c4];
        float4 o;
        o.x = fmaxf(fmaf(v.x, sc.x, sh.x), 0.f);
        o.y = fmaxf(fmaf(v.y, sc.y, sh.y), 0.f);
        o.z = fmaxf(fmaf(v.z, sc.z, sh.z), 0.f);
        o.w = fmaxf(fmaf(v.w, sc.w, sh.w), 0.f);
        ((float4*)O)[i] = o;
    }
}

// ---------------- weight prep ----------------------------------------------
__global__ void round_tf32(const float* __restrict__ src,
                           unsigned* __restrict__ dst, int n) {
    int i = blockIdx.x * blockDim.x + threadIdx.x;
    if (i < n) dst[i] = f2tf32(src[i]);
}

// g_wct rows 0..255 = tf32(W3 @ We); rows 256..383 = tf32(We)
__global__ void build_wct(const float* __restrict__ W3,
                          const float* __restrict__ We) {
    __shared__ float row[128];
    int k = blockIdx.x;       // 0..383
    int c = threadIdx.x;      // 0..127
    if (k >= 256) {
        g_wct[k * 128 + c] = f2tf32(We[(k - 256) * 128 + c]);
        return;
    }
    row[c] = W3[k * 128 + c];
    __syncthreads();
    float s = 0.f;
#pragma unroll 8
    for (int j = 0; j < 128; j++) s = fmaf(row[j], We[j * 128 + c], s);
    g_wct[k * 128 + c] = f2tf32(s);
}

// bc = b3 @ We + be   (b3 is length C=128)
__global__ void build_bc(const float* __restrict__ b3,
                         const float* __restrict__ We,
                         const float* __restrict__ be) {
    __shared__ float row[128];
    int c = threadIdx.x;      // 0..127
    row[c] = b3[c];
    __syncthreads();
    float s = be[c];
#pragma unroll 8
    for (int j = 0; j < 128; j++) s = fmaf(row[j], We[j * 128 + c], s);
    g_bc[c] = s;
}

// ---------------- CSR build (counting sort by dst) -------------------------
__global__ void hist(const int* __restrict__ ei) {
    int e = blockIdx.x * blockDim.x + threadIdx.x;
    if (e < N_EDGES) atomicAdd(&g_cnt[ei[N_EDGES + e]], 1);
}

__global__ void scan_sums() {
    __shared__ int sh[SCAN_B];
    int gi = blockIdx.x * SCAN_B + threadIdx.x;
    sh[threadIdx.x] = (gi < N_NODES) ? g_cnt[gi] : 0;
    __syncthreads();
    for (int ofs = SCAN_B / 2; ofs > 0; ofs >>= 1) {
        if (threadIdx.x < ofs) sh[threadIdx.x] += sh[threadIdx.x + ofs];
        __syncthreads();
    }
    if (threadIdx.x == 0) g_bsum[blockIdx.x] = sh[0];
}

__global__ void scan_bsum() {
    __shared__ int sh[NSCAN];
    int t = threadIdx.x;
    if (t < NSCAN) sh[t] = g_bsum[t];
    __syncthreads();
    if (t == 0) {
        int run = 0;
        for (int i = 0; i < NSCAN; i++) { int v = sh[i]; sh[i] = run; run += v; }
        g_off[N_NODES] = run;
    }
    __syncthreads();
    if (t < NSCAN) g_bsum[t] = sh[t];
}

__global__ void scan_final() {
    __shared__ int sh[2][SCAN_B];
    int b = blockIdx.x, t = threadIdx.x;
    int gi = b * SCAN_B + t;
    int v = (gi < N_NODES) ? g_cnt[gi] : 0;
    sh[0][t] = v;
    __syncthreads();
    int src = 0;
    for (int ofs = 1; ofs < SCAN_B; ofs <<= 1) {
        int nv = sh[src][t] + ((t >= ofs) ? sh[src][t - ofs] : 0);
        sh[src ^ 1][t] = nv;
        __syncthreads();
        src ^= 1;
    }
    int excl = sh[src][t] - v;  // exclusive scan
    if (gi < N_NODES) {
        int o = g_bsum[b] + excl;
        g_off[gi] = o;
        g_cur[gi] = o;
        g_cnt[gi] = 0;          // self-zero for next replay's hist
    }
}

__global__ void scatter(const int* __restrict__ ei) {
    int e = blockIdx.x * blockDim.x + threadIdx.x;
    if (e < N_EDGES) {
        int d = ei[N_EDGES + e];
        int p = atomicAdd(&g_cur[d], 1);
        g_srcs[p] = ei[e];
    }
}

// ---------------- aggregation: warp per dst node, zero atomics -------------
__global__ void agg_kernel(const float* __restrict__ h, float* __restrict__ om) {
    int warp = (blockIdx.x * blockDim.x + threadIdx.x) >> 5;
    int lane = threadIdx.x & 31;
    if (warp >= N_NODES) return;
    int j0 = g_off[warp], j1 = g_off[warp + 1];
    float4 den = make_float4(0.f, 0.f, 0.f, 0.f);
    float4 num = make_float4(0.f, 0.f, 0.f, 0.f);
    for (int j = j0; j < j1; j++) {
        int s = g_srcs[j];
        float4 v = __ldg((const float4*)(h + (size_t)s * C) + lane);
        float m0 = v.x + EPS_GEN, m1 = v.y + EPS_GEN;
        float m2 = v.z + EPS_GEN, m3 = v.w + EPS_GEN;
        float e0 = __expf(m0), e1 = __expf(m1);
        float e2 = __expf(m2), e3 = __expf(m3);
        den.x += e0; den.y += e1; den.z += e2; den.w += e3;
        num.x += m0 * e0; num.y += m1 * e1; num.z += m2 * e2; num.w += m3 * e3;
    }
    float4 hd = ((const float4*)(h + (size_t)warp * C))[lane];
    float4 o;
    o.x = num.x / (den.x + 1e-16f) + hd.x;
    o.y = num.y / (den.y + 1e-16f) + hd.y;
    o.z = num.z / (den.z + 1e-16f) + hd.z;
    o.w = num.w / (den.w + 1e-16f) + hd.w;
    ((float4*)(om + (size_t)warp * C))[lane] = o;
}

// ---------------- tf32 tensor-core GEMM ------------------------------------
// C[M,N] = op(A|A2)[M,K] @ Bt[K,N] + bias.  Bt is PRE-ROUNDED tf32 bits,
// staged smem<-global via cp.async (overlaps MMA, no regs, no conflicts).
// A: LDG -> (PRE: relu(a*scale+shift)) -> cvt tf32 -> STS (pad 137 => both
// stores and fragment loads conflict-free).
__device__ __forceinline__ void cpasync16(uint32_t daddr, const void* gptr) {
    asm volatile("cp.async.ca.shared.global [%0], [%1], 16;"
                 :: "r"(daddr), "l"(gptr));
}

template <bool PRE, bool STATS>
__global__ __launch_bounds__(256, 2)
void gemm_tc(const float* __restrict__ A, int lda,
             const float* __restrict__ A2, int lda2, int Ksplit,
             const unsigned* __restrict__ Bt,
             const float* __restrict__ bias,
             float* __restrict__ Cout, int M, int Ncols, int K) {
    __shared__ unsigned As[2][16][137];  // [buf][k][m]
    __shared__ unsigned Bs[2][16][140];  // [buf][k][n], 140*4B = 16B-aligned rows
    __shared__ float smS[128], smQ[128];

    int tid = threadIdx.x;
    int warpId = tid >> 5, lane = tid & 31;
    int grp = lane >> 2, tig = lane & 3;
    int wm = (warpId >> 2) * 64;
    int wn = (warpId & 3) * 32;
    int rowBase = blockIdx.y * 128;
    int colBase = blockIdx.x * 128;

    // A staging: element i = tid + s*256 -> m = i>>2, kq = i&3
    int am  = tid >> 2, akq0 = tid & 3;
    int am1 = (tid + 256) >> 2;
    // B staging (cp.async): chunk c = tid + s*256 -> k = c>>5, n4 = (c&31)*4
    int bka = tid >> 5,          bna = (tid & 31) * 4;
    int bkb = (tid + 256) >> 5,  bnb = bna;

    float4 va0, va1;

    auto ldA = [&](int k0) {
        int kk = k0 + akq0 * 4;
        const float4 z = make_float4(0.f, 0.f, 0.f, 0.f);
        int r0 = rowBase + am, r1 = rowBase + am1;
        if (A2 != nullptr && k0 >= Ksplit) {
            int kr = kk - Ksplit;
            va0 = (r0 < M) ? *(const float4*)(A2 + (size_t)r0 * lda2 + kr) : z;
            va1 = (r1 < M) ? *(const float4*)(A2 + (size_t)r1 * lda2 + kr) : z;
        } else {
            va0 = (r0 < M) ? *(const float4*)(A + (size_t)r0 * lda + kk) : z;
            va1 = (r1 < M) ? *(const float4*)(A + (size_t)r1 * lda + kk) : z;
        }
    };
    auto stsA = [&](int buf, int k0) {
        int kk = akq0 * 4;
        float4 v0 = va0, v1 = va1;
        if (PRE && k0 < Ksplit) {
            float s0 = g_scale[k0 + kk + 0], h0 = g_shift[k0 + kk + 0];
            float s1 = g_scale[k0 + kk + 1], h1 = g_shift[k0 + kk + 1];
            float s2 = g_scale[k0 + kk + 2], h2 = g_shift[k0 + kk + 2];
            float s3 = g_scale[k0 + kk + 3], h3 = g_shift[k0 + kk + 3];
            v0.x = fmaxf(fmaf(v0.x, s0, h0), 0.f);
            v0.y = fmaxf(fmaf(v0.y, s1, h1), 0.f);
            v0.z = fmaxf(fmaf(v0.z, s2, h2), 0.f);
            v0.w = fmaxf(fmaf(v0.w, s3, h3), 0.f);
            v1.x = fmaxf(fmaf(v1.x, s0, h0), 0.f);
            v1.y = fmaxf(fmaf(v1.y, s1, h1), 0.f);
            v1.z = fmaxf(fmaf(v1.z, s2, h2), 0.f);
            v1.w = fmaxf(fmaf(v1.w, s3, h3), 0.f);
        }
        As[buf][kk + 0][am]  = f2tf32(v0.x);
        As[buf][kk + 1][am]  = f2tf32(v0.y);
        As[buf][kk + 2][am]  = f2tf32(v0.z);
        As[buf][kk + 3][am]  = f2tf32(v0.w);
        As[buf][kk + 0][am1] = f2tf32(v1.x);
        As[buf][kk + 1][am1] = f2tf32(v1.y);
        As[buf][kk + 2][am1] = f2tf32(v1.z);
        As[buf][kk + 3][am1] = f2tf32(v1.w);
    };
    auto cpB = [&](int buf, int k0) {
        cpasync16((uint32_t)__cvta_generic_to_shared(&Bs[buf][bka][bna]),
                  Bt + (size_t)(k0 + bka) * Ncols + colBase + bna);
        cpasync16((uint32_t)__cvta_generic_to_shared(&Bs[buf][bkb][bnb]),
                  Bt + (size_t)(k0 + bkb) * Ncols + colBase + bnb);
        asm volatile("cp.async.commit_group;");
    };

    float acc[4][4][4];
#pragma unroll
    for (int i = 0; i < 4; i++)
#pragma unroll
        for (int j = 0; j < 4; j++)
#pragma unroll
            for (int r = 0; r < 4; r++) acc[i][j][r] = 0.f;

    cpB(0, 0);
    ldA(0);
    stsA(0, 0);
    asm volatile("cp.async.wait_group 0;" ::: "memory");
    __syncthreads();

    int nt = K / 16;
    for (int kt = 0; kt < nt; kt++) {
        int buf = kt & 1;
        bool more = (kt + 1 < nt);
        if (more) { ldA((kt + 1) * 16); cpB(buf ^ 1, (kt + 1) * 16); }

#pragma unroll
        for (int ks = 0; ks < 16; ks += 8) {
            unsigned a[4][4], b[4][2];
#pragma unroll
            for (int i = 0; i < 4; i++) {
                int r0 = wm + 16 * i + grp;
                a[i][0] = As[buf][ks + tig][r0];
                a[i][1] = As[buf][ks + tig][r0 + 8];
                a[i][2] = As[buf][ks + tig + 4][r0];
                a[i][3] = As[buf][ks + tig + 4][r0 + 8];
            }
#pragma unroll
            for (int j = 0; j < 4; j++) {
                int cn = wn + 8 * j + grp;
                b[j][0] = Bs[buf][ks + tig][cn];
                b[j][1] = Bs[buf][ks + tig + 4][cn];
            }
#pragma unroll
            for (int i = 0; i < 4; i++)
#pragma unroll
                for (int j = 0; j < 4; j++)
                    asm volatile(
                        "mma.sync.aligned.m16n8k8.row.col.f32.tf32.tf32.f32 "
                        "{%0,%1,%2,%3}, {%4,%5,%6,%7}, {%8,%9}, {%0,%1,%2,%3};"
                        : "+f"(acc[i][j][0]), "+f"(acc[i][j][1]),
                          "+f"(acc[i][j][2]), "+f"(acc[i][j][3])
                        : "r"(a[i][0]), "r"(a[i][1]), "r"(a[i][2]), "r"(a[i][3]),
                          "r"(b[j][0]), "r"(b[j][1]));
        }

        if (more) {
            stsA(buf ^ 1, (kt + 1) * 16);
            asm volatile("cp.async.wait_group 0;" ::: "memory");
            __syncthreads();
        }
    }

    if (STATS) {
        __syncthreads();
        if (tid < 128) { smS[tid] = 0.f; smQ[tid] = 0.f; }
        __syncthreads();
    }

#pragma unroll
    for (int j = 0; j < 4; j++) {
        int colL = wn + 8 * j + 2 * tig;
        int col = colBase + colL;
        float b0 = bias[col], b1 = bias[col + 1];
        float s0 = 0.f, q0 = 0.f, s1 = 0.f, q1 = 0.f;
#pragma unroll
        for (int i = 0; i < 4; i++) {
            int r0 = rowBase + wm + 16 * i + grp;
            int r1 = r0 + 8;
            if (r0 < M) {
                float v0 = acc[i][j][0] + b0;
                float v1 = acc[i][j][1] + b1;
                *(float2*)(Cout + (size_t)r0 * Ncols + col) = make_float2(v0, v1);
                s0 += v0; q0 += v0 * v0; s1 += v1; q1 += v1 * v1;
            }
            if (r1 < M) {
                float v0 = acc[i][j][2] + b0;
                float v1 = acc[i][j][3] + b1;
                *(float2*)(Cout + (size_t)r1 * Ncols + col) = make_float2(v0, v1);
                s0 += v0; q0 += v0 * v0; s1 += v1; q1 += v1 * v1;
            }
        }
        if (STATS) {
            atomicAdd(&smS[colL], s0);
            atomicAdd(&smQ[colL], q0);
            atomicAdd(&smS[colL + 1], s1);
            atomicAdd(&smQ[colL + 1], q1);
        }
    }
    if (STATS) {
        __syncthreads();
        if (tid < 128) {
            atomicAdd(&g_sum[colBase + tid], smS[tid]);
            atomicAdd(&g_sumsq[colBase + tid], smQ[tid]);
        }
    }
}

// ---------------- launch ----------------------------------------------------
extern "C" void kernel_launch(void* const* d_in, const int* in_sizes, int n_in,
                              void* d_out, int out_size) {
    const float* x    = (const float*)d_in[0];
    const int*   ei   = (const int*)d_in[1];   // int32 (JAX x64 disabled)
    const float* bn_g = (const float*)d_in[2];
    const float* bn_b = (const float*)d_in[3];
    const float* W1   = (const float*)d_in[4];
    const float* b1   = (const float*)d_in[5];
    const float* g1   = (const float*)d_in[6];
    const float* be1  = (const float*)d_in[7];
    const float* W2   = (const float*)d_in[8];
    const float* b2   = (const float*)d_in[9];
    const float* g2   = (const float*)d_in[10];
    const float* be2  = (const float*)d_in[11];
    const float* W3   = (const float*)d_in[12];
    const float* b3   = (const float*)d_in[13];
    const float* We   = (const float*)d_in[14];
    const float* be   = (const float*)d_in[15];
    float* out = (float*)d_out;

    float* p_h;    cudaGetSymbolAddress((void**)&p_h,   g_h);
    float* p_min;  cudaGetSymbolAddress((void**)&p_min, g_min);
    float* p_y0;   cudaGetSymbolAddress((void**)&p_y0,  g_y0);
    float* p_y1;   cudaGetSymbolAddress((void**)&p_y1,  g_y1);
    unsigned* p_w1t; cudaGetSymbolAddress((void**)&p_w1t, g_w1t);
    unsigned* p_w2t; cudaGetSymbolAddress((void**)&p_w2t, g_w2t);
    unsigned* p_wct; cudaGetSymbolAddress((void**)&p_wct, g_wct);
    float* p_bc;   cudaGetSymbolAddress((void**)&p_bc,  g_bc);

    const int EW = 256;
    int nNC = N_NODES * C;
    dim3 gemmGridH(2, (N_NODES + 127) / 128);   // N = 256
    dim3 gemmGridC(1, (N_NODES + 127) / 128);   // N = 128

    // --- BN(x) -> h  (g_sum/g_sumsq arrive zeroed; finalize re-zeroes) ---
    colstats<<<512, C>>>(x, N_NODES, C);
    finalize_stats<<<1, C>>>(C, N_NODES, bn_g, bn_b);
    bn_relu4<<<(nNC / 4 + EW - 1) / EW, EW>>>(x, p_h, nNC / 4, C / 4 - 1);

    // --- weight prep: tf32 rounding + combined layer3/encoder ---
    round_tf32<<<(C * H + EW - 1) / EW, EW>>>(W1, p_w1t, C * H);
    round_tf32<<<(H * H + EW - 1) / EW, EW>>>(W2, p_w2t, H * H);
    build_wct<<<384, 128>>>(W3, We);
    build_bc<<<1, 128>>>(b3, We, be);

    // --- build dst-CSR (counting sort; g_cnt arrives zeroed) ---
    hist<<<(N_EDGES + EW - 1) / EW, EW>>>(ei);
    scan_sums<<<NSCAN, SCAN_B>>>();
    scan_bsum<<<1, 128>>>();
    scan_final<<<NSCAN, SCAN_B>>>();
    scatter<<<(N_EDGES + EW - 1) / EW, EW>>>(ei);

    // --- softmax aggregation + root add (warp per node) ---
    agg_kernel<<<N_NODES / 8, 256>>>(p_h, p_min);

    // --- MLP layer 1: y0 = mlp_in @ W1 + b1 (stats fused) ---
    gemm_tc<false, true><<<gemmGridH, 256>>>(
        p_min, C, nullptr, 0, C, p_w1t, b1, p_y0, N_NODES, H, C);
    finalize_stats<<<1, H>>>(H, N_NODES, g1, be1);

    // --- MLP layer 2: y1 = relu(BN(y0)) @ W2 + b2 (pre + stats fused) ---
    gemm_tc<true, true><<<gemmGridH, 256>>>(
        p_y0, H, nullptr, 0, H, p_w2t, b2, p_y1, N_NODES, H, H);
    finalize_stats<<<1, H>>>(H, N_NODES, g2, be2);

    // --- fused layer3+encoder: out = [relu(BN(y1)) | x] @ Wc + bc ---
    gemm_tc<true, false><<<gemmGridC, 256>>>(
        p_y1, H, x, C, H, p_wct, p_bc, out, N_NODES, C, H + C);
}

// round 16
// speedup vs baseline: 1.0027x; 1.0027x over previous
#include <cuda_runtime.h>
#include <cstdint>

// Problem constants (fixed by the reference)
#define N_NODES 50000
#define N_EDGES 600000
#define C 128
#define H 256
#define EPS_GEN 1e-7f
#define EPS_BN  1e-5f

// ---------------- scratch (device globals; no allocation allowed) ----------
__device__ float g_h  [N_NODES * C];   // relu(BN(x))
__device__ float g_min[N_NODES * C];   // mlp input = agg + h
__device__ float g_y0 [N_NODES * H];
__device__ float g_y1 [N_NODES * H];
__device__ float g_sum[H];             // zero-init; self-zeroed by finalize
__device__ float g_sumsq[H];
__device__ float g_scale[H];
__device__ float g_shift[H];
__device__ unsigned g_w1t[C * H];      // tf32-rounded W1
__device__ unsigned g_w2t[H * H];      // tf32-rounded W2
__device__ unsigned g_wct[384 * 128];  // tf32-rounded [W3@We ; We]
__device__ float g_bc [128];           // b3@We + be

// CSR-by-dst scratch
#define SCAN_B 512
#define NSCAN ((N_NODES + SCAN_B - 1) / SCAN_B)
__device__ int g_cnt [N_NODES];        // zero-init; self-zeroed by scan_final
__device__ int g_cur [N_NODES];
__device__ int g_off [N_NODES + 1];
__device__ int g_bsum[NSCAN];
__device__ int g_srcs[N_EDGES];

__device__ __forceinline__ unsigned f2tf32(float v) {
    unsigned u;
    asm("cvt.rna.tf32.f32 %0, %1;" : "=r"(u) : "f"(v));
    return u;
}

// ---------------- BN utility kernels ---------------------------------------
__global__ void colstats(const float* __restrict__ A, int rows, int Ccols) {
    int c = threadIdx.x;
    float s = 0.f, sq = 0.f;
    for (int r = blockIdx.x; r < rows; r += gridDim.x) {
        float v = A[(size_t)r * Ccols + c];
        s += v;
        sq += v * v;
    }
    atomicAdd(&g_sum[c], s);
    atomicAdd(&g_sumsq[c], sq);
}

__global__ void finalize_stats(int Ccols, int rows,
                               const float* __restrict__ g,
                               const float* __restrict__ b) {
    int c = threadIdx.x;
    if (c < Ccols) {
        float mean = g_sum[c] / rows;
        float var  = g_sumsq[c] / rows - mean * mean;
        float rs   = rsqrtf(var + EPS_BN);
        float sc   = rs * g[c];
        g_scale[c] = sc;
        g_shift[c] = b[c] - mean * sc;
        g_sum[c]   = 0.f;   // self-zero for next consumer / next replay
        g_sumsq[c] = 0.f;
    }
}

// h = relu(x*scale + shift), float4-vectorized
__global__ void bn_relu4(const float* __restrict__ A, float* __restrict__ O,
                         int total4, int cmask4) {
    int i = blockIdx.x * blockDim.x + threadIdx.x;
    int stride = gridDim.x * blockDim.x;
    for (; i < total4; i += stride) {
        int c4 = (i & cmask4) * 4;
        float4 v  = ((const float4*)A)[i];
        float4 sc = *(const float4*)&g_scale[c4];
        float4 sh = *(const float4*)&g_shift[c4];
        float4 o;
        o.x = fmaxf(fmaf(v.x, sc.x, sh.x), 0.f);
        o.y = fmaxf(fmaf(v.y, sc.y, sh.y), 0.f);
        o.z = fmaxf(fmaf(v.z, sc.z, sh.z), 0.f);
        o.w = fmaxf(fmaf(v.w, sc.w, sh.w), 0.f);
        ((float4*)O)[i] = o;
    }
}

// ---------------- weight prep ----------------------------------------------
// One launch rounds BOTH W1 (C*H) and W2 (H*H) to tf32 bits.
__global__ void round_w12(const float* __restrict__ W1,
                          const float* __restrict__ W2) {
    int i = blockIdx.x * blockDim.x + threadIdx.x;
    int stride = gridDim.x * blockDim.x;
    const int n1 = C * H, n2 = H * H;
    for (; i < n1 + n2; i += stride) {
        if (i < n1) g_w1t[i] = f2tf32(W1[i]);
        else        g_w2t[i - n1] = f2tf32(W2[i - n1]);
    }
}

// g_wct rows 0..255 = tf32(W3 @ We); rows 256..383 = tf32(We)
__global__ void build_wct(const float* __restrict__ W3,
                          const float* __restrict__ We) {
    __shared__ float row[128];
    int k = blockIdx.x;       // 0..383
    int c = threadIdx.x;      // 0..127
    if (k >= 256) {
        g_wct[k * 128 + c] = f2tf32(We[(k - 256) * 128 + c]);
        return;
    }
    row[c] = W3[k * 128 + c];
    __syncthreads();
    float s = 0.f;
#pragma unroll 8
    for (int j = 0; j < 128; j++) s = fmaf(row[j], We[j * 128 + c], s);
    g_wct[k * 128 + c] = f2tf32(s);
}

// bc = b3 @ We + be   (b3 is length C=128)
__global__ void build_bc(const float* __restrict__ b3,
                         const float* __restrict__ We,
                         const float* __restrict__ be) {
    __shared__ float row[128];
    int c = threadIdx.x;      // 0..127
    row[c] = b3[c];
    __syncthreads();
    float s = be[c];
#pragma unroll 8
    for (int j = 0; j < 128; j++) s = fmaf(row[j], We[j * 128 + c], s);
    g_bc[c] = s;
}

// ---------------- CSR build (counting sort by dst) -------------------------
__global__ void hist(const int* __restrict__ ei) {
    int e = blockIdx.x * blockDim.x + threadIdx.x;
    if (e < N_EDGES) atomicAdd(&g_cnt[ei[N_EDGES + e]], 1);
}

__global__ void scan_sums() {
    __shared__ int sh[SCAN_B];
    int gi = blockIdx.x * SCAN_B + threadIdx.x;
    sh[threadIdx.x] = (gi < N_NODES) ? g_cnt[gi] : 0;
    __syncthreads();
    for (int ofs = SCAN_B / 2; ofs > 0; ofs >>= 1) {
        if (threadIdx.x < ofs) sh[threadIdx.x] += sh[threadIdx.x + ofs];
        __syncthreads();
    }
    if (threadIdx.x == 0) g_bsum[blockIdx.x] = sh[0];
}

__global__ void scan_bsum() {
    __shared__ int sh[NSCAN];
    int t = threadIdx.x;
    if (t < NSCAN) sh[t] = g_bsum[t];
    __syncthreads();
    if (t == 0) {
        int run = 0;
        for (int i = 0; i < NSCAN; i++) { int v = sh[i]; sh[i] = run; run += v; }
        g_off[N_NODES] = run;
    }
    __syncthreads();
    if (t < NSCAN) g_bsum[t] = sh[t];
}

__global__ void scan_final() {
    __shared__ int sh[2][SCAN_B];
    int b = blockIdx.x, t = threadIdx.x;
    int gi = b * SCAN_B + t;
    int v = (gi < N_NODES) ? g_cnt[gi] : 0;
    sh[0][t] = v;
    __syncthreads();
    int src = 0;
    for (int ofs = 1; ofs < SCAN_B; ofs <<= 1) {
        int nv = sh[src][t] + ((t >= ofs) ? sh[src][t - ofs] : 0);
        sh[src ^ 1][t] = nv;
        __syncthreads();
        src ^= 1;
    }
    int excl = sh[src][t] - v;  // exclusive scan
    if (gi < N_NODES) {
        int o = g_bsum[b] + excl;
        g_off[gi] = o;
        g_cur[gi] = o;
        g_cnt[gi] = 0;          // self-zero for next replay's hist
    }
}

__global__ void scatter(const int* __restrict__ ei) {
    int e = blockIdx.x * blockDim.x + threadIdx.x;
    if (e < N_EDGES) {
        int d = ei[N_EDGES + e];
        int p = atomicAdd(&g_cur[d], 1);
        g_srcs[p] = ei[e];
    }
}

// ---------------- aggregation: warp per dst node, zero atomics -------------
__global__ void agg_kernel(const float* __restrict__ h, float* __restrict__ om) {
    int warp = (blockIdx.x * blockDim.x + threadIdx.x) >> 5;
    int lane = threadIdx.x & 31;
    if (warp >= N_NODES) return;
    int j0 = g_off[warp], j1 = g_off[warp + 1];
    float4 den = make_float4(0.f, 0.f, 0.f, 0.f);
    float4 num = make_float4(0.f, 0.f, 0.f, 0.f);
    for (int j = j0; j < j1; j++) {
        int s = g_srcs[j];
        float4 v = __ldg((const float4*)(h + (size_t)s * C) + lane);
        float m0 = v.x + EPS_GEN, m1 = v.y + EPS_GEN;
        float m2 = v.z + EPS_GEN, m3 = v.w + EPS_GEN;
        float e0 = __expf(m0), e1 = __expf(m1);
        float e2 = __expf(m2), e3 = __expf(m3);
        den.x += e0; den.y += e1; den.z += e2; den.w += e3;
        num.x += m0 * e0; num.y += m1 * e1; num.z += m2 * e2; num.w += m3 * e3;
    }
    float4 hd = ((const float4*)(h + (size_t)warp * C))[lane];
    float4 o;
    o.x = num.x / (den.x + 1e-16f) + hd.x;
    o.y = num.y / (den.y + 1e-16f) + hd.y;
    o.z = num.z / (den.z + 1e-16f) + hd.z;
    o.w = num.w / (den.w + 1e-16f) + hd.w;
    ((float4*)(om + (size_t)warp * C))[lane] = o;
}

// ---------------- tf32 tensor-core GEMM ------------------------------------
// C[M,N] = op(A|A2)[M,K] @ Bt[K,N] + bias.  Bt is PRE-ROUNDED tf32 bits,
// staged smem<-global via cp.async. A: LDG -> (PRE) -> cvt -> STS (pad 137).
// NO min-blocks cap: let ptxas keep full registers (spills cost more than
// the 2nd CTA gains — R13 lesson).
__device__ __forceinline__ void cpasync16(uint32_t daddr, const void* gptr) {
    asm volatile("cp.async.ca.shared.global [%0], [%1], 16;"
                 :: "r"(daddr), "l"(gptr));
}

template <bool PRE, bool STATS>
__global__ __launch_bounds__(256)
void gemm_tc(const float* __restrict__ A, int lda,
             const float* __restrict__ A2, int lda2, int Ksplit,
             const unsigned* __restrict__ Bt,
             const float* __restrict__ bias,
             float* __restrict__ Cout, int M, int Ncols, int K) {
    __shared__ unsigned As[2][16][137];  // [buf][k][m]
    __shared__ unsigned Bs[2][16][140];  // [buf][k][n], 140*4B = 16B-aligned rows
    __shared__ float smS[128], smQ[128];

    int tid = threadIdx.x;
    int warpId = tid >> 5, lane = tid & 31;
    int grp = lane >> 2, tig = lane & 3;
    int wm = (warpId >> 2) * 64;
    int wn = (warpId & 3) * 32;
    int rowBase = blockIdx.y * 128;
    int colBase = blockIdx.x * 128;

    // A staging: element i = tid + s*256 -> m = i>>2, kq = i&3
    int am  = tid >> 2, akq0 = tid & 3;
    int am1 = (tid + 256) >> 2;
    // B staging (cp.async): chunk c = tid + s*256 -> k = c>>5, n4 = (c&31)*4
    int bka = tid >> 5,          bna = (tid & 31) * 4;
    int bkb = (tid + 256) >> 5,  bnb = bna;

    float4 va0, va1;

    auto ldA = [&](int k0) {
        int kk = k0 + akq0 * 4;
        const float4 z = make_float4(0.f, 0.f, 0.f, 0.f);
        int r0 = rowBase + am, r1 = rowBase + am1;
        if (A2 != nullptr && k0 >= Ksplit) {
            int kr = kk - Ksplit;
            va0 = (r0 < M) ? *(const float4*)(A2 + (size_t)r0 * lda2 + kr) : z;
            va1 = (r1 < M) ? *(const float4*)(A2 + (size_t)r1 * lda2 + kr) : z;
        } else {
            va0 = (r0 < M) ? *(const float4*)(A + (size_t)r0 * lda + kk) : z;
            va1 = (r1 < M) ? *(const float4*)(A + (size_t)r1 * lda + kk) : z;
        }
    };
    auto stsA = [&](int buf, int k0) {
        int kk = akq0 * 4;
        float4 v0 = va0, v1 = va1;
        if (PRE && k0 < Ksplit) {
            float s0 = g_scale[k0 + kk + 0], h0 = g_shift[k0 + kk + 0];
            float s1 = g_scale[k0 + kk + 1], h1 = g_shift[k0 + kk + 1];
            float s2 = g_scale[k0 + kk + 2], h2 = g_shift[k0 + kk + 2];
            float s3 = g_scale[k0 + kk + 3], h3 = g_shift[k0 + kk + 3];
            v0.x = fmaxf(fmaf(v0.x, s0, h0), 0.f);
            v0.y = fmaxf(fmaf(v0.y, s1, h1), 0.f);
            v0.z = fmaxf(fmaf(v0.z, s2, h2), 0.f);
            v0.w = fmaxf(fmaf(v0.w, s3, h3), 0.f);
            v1.x = fmaxf(fmaf(v1.x, s0, h0), 0.f);
            v1.y = fmaxf(fmaf(v1.y, s1, h1), 0.f);
            v1.z = fmaxf(fmaf(v1.z, s2, h2), 0.f);
            v1.w = fmaxf(fmaf(v1.w, s3, h3), 0.f);
        }
        As[buf][kk + 0][am]  = f2tf32(v0.x);
        As[buf][kk + 1][am]  = f2tf32(v0.y);
        As[buf][kk + 2][am]  = f2tf32(v0.z);
        As[buf][kk + 3][am]  = f2tf32(v0.w);
        As[buf][kk + 0][am1] = f2tf32(v1.x);
        As[buf][kk + 1][am1] = f2tf32(v1.y);
        As[buf][kk + 2][am1] = f2tf32(v1.z);
        As[buf][kk + 3][am1] = f2tf32(v1.w);
    };
    auto cpB = [&](int buf, int k0) {
        cpasync16((uint32_t)__cvta_generic_to_shared(&Bs[buf][bka][bna]),
                  Bt + (size_t)(k0 + bka) * Ncols + colBase + bna);
        cpasync16((uint32_t)__cvta_generic_to_shared(&Bs[buf][bkb][bnb]),
                  Bt + (size_t)(k0 + bkb) * Ncols + colBase + bnb);
        asm volatile("cp.async.commit_group;");
    };

    float acc[4][4][4];
#pragma unroll
    for (int i = 0; i < 4; i++)
#pragma unroll
        for (int j = 0; j < 4; j++)
#pragma unroll
            for (int r = 0; r < 4; r++) acc[i][j][r] = 0.f;

    cpB(0, 0);
    ldA(0);
    stsA(0, 0);
    asm volatile("cp.async.wait_group 0;" ::: "memory");
    __syncthreads();

    int nt = K / 16;
    for (int kt = 0; kt < nt; kt++) {
        int buf = kt & 1;
        bool more = (kt + 1 < nt);
        if (more) { ldA((kt + 1) * 16); cpB(buf ^ 1, (kt + 1) * 16); }

#pragma unroll
        for (int ks = 0; ks < 16; ks += 8) {
            unsigned a[4][4], b[4][2];
#pragma unroll
            for (int i = 0; i < 4; i++) {
                int r0 = wm + 16 * i + grp;
                a[i][0] = As[buf][ks + tig][r0];
                a[i][1] = As[buf][ks + tig][r0 + 8];
                a[i][2] = As[buf][ks + tig + 4][r0];
                a[i][3] = As[buf][ks + tig + 4][r0 + 8];
            }
#pragma unroll
            for (int j = 0; j < 4; j++) {
                int cn = wn + 8 * j + grp;
                b[j][0] = Bs[buf][ks + tig][cn];
                b[j][1] = Bs[buf][ks + tig + 4][cn];
            }
#pragma unroll
            for (int i = 0; i < 4; i++)
#pragma unroll
                for (int j = 0; j < 4; j++)
                    asm volatile(
                        "mma.sync.aligned.m16n8k8.row.col.f32.tf32.tf32.f32 "
                        "{%0,%1,%2,%3}, {%4,%5,%6,%7}, {%8,%9}, {%0,%1,%2,%3};"
                        : "+f"(acc[i][j][0]), "+f"(acc[i][j][1]),
                          "+f"(acc[i][j][2]), "+f"(acc[i][j][3])
                        : "r"(a[i][0]), "r"(a[i][1]), "r"(a[i][2]), "r"(a[i][3]),
                          "r"(b[j][0]), "r"(b[j][1]));
        }

        if (more) {
            stsA(buf ^ 1, (kt + 1) * 16);
            asm volatile("cp.async.wait_group 0;" ::: "memory");
            __syncthreads();
        }
    }

    if (STATS) {
        __syncthreads();
        if (tid < 128) { smS[tid] = 0.f; smQ[tid] = 0.f; }
        __syncthreads();
    }

#pragma unroll
    for (int j = 0; j < 4; j++) {
        int colL = wn + 8 * j + 2 * tig;
        int col = colBase + colL;
        float b0 = bias[col], b1 = bias[col + 1];
        float s0 = 0.f, q0 = 0.f, s1 = 0.f, q1 = 0.f;
#pragma unroll
        for (int i = 0; i < 4; i++) {
            int r0 = rowBase + wm + 16 * i + grp;
            int r1 = r0 + 8;
            if (r0 < M) {
                float v0 = acc[i][j][0] + b0;
                float v1 = acc[i][j][1] + b1;
                *(float2*)(Cout + (size_t)r0 * Ncols + col) = make_float2(v0, v1);
                s0 += v0; q0 += v0 * v0; s1 += v1; q1 += v1 * v1;
            }
            if (r1 < M) {
                float v0 = acc[i][j][2] + b0;
                float v1 = acc[i][j][3] + b1;
                *(float2*)(Cout + (size_t)r1 * Ncols + col) = make_float2(v0, v1);
                s0 += v0; q0 += v0 * v0; s1 += v1; q1 += v1 * v1;
            }
        }
        if (STATS) {
            atomicAdd(&smS[colL], s0);
            atomicAdd(&smQ[colL], q0);
            atomicAdd(&smS[colL + 1], s1);
            atomicAdd(&smQ[colL + 1], q1);
        }
    }
    if (STATS) {
        __syncthreads();
        if (tid < 128) {
            atomicAdd(&g_sum[colBase + tid], smS[tid]);
            atomicAdd(&g_sumsq[colBase + tid], smQ[tid]);
        }
    }
}

// ---------------- launch ----------------------------------------------------
extern "C" void kernel_launch(void* const* d_in, const int* in_sizes, int n_in,
                              void* d_out, int out_size) {
    const float* x    = (const float*)d_in[0];
    const int*   ei   = (const int*)d_in[1];   // int32 (JAX x64 disabled)
    const float* bn_g = (const float*)d_in[2];
    const float* bn_b = (const float*)d_in[3];
    const float* W1   = (const float*)d_in[4];
    const float* b1   = (const float*)d_in[5];
    const float* g1   = (const float*)d_in[6];
    const float* be1  = (const float*)d_in[7];
    const float* W2   = (const float*)d_in[8];
    const float* b2   = (const float*)d_in[9];
    const float* g2   = (const float*)d_in[10];
    const float* be2  = (const float*)d_in[11];
    const float* W3   = (const float*)d_in[12];
    const float* b3   = (const float*)d_in[13];
    const float* We   = (const float*)d_in[14];
    const float* be   = (const float*)d_in[15];
    float* out = (float*)d_out;

    float* p_h;    cudaGetSymbolAddress((void**)&p_h,   g_h);
    float* p_min;  cudaGetSymbolAddress((void**)&p_min, g_min);
    float* p_y0;   cudaGetSymbolAddress((void**)&p_y0,  g_y0);
    float* p_y1;   cudaGetSymbolAddress((void**)&p_y1,  g_y1);
    unsigned* p_w1t; cudaGetSymbolAddress((void**)&p_w1t, g_w1t);
    unsigned* p_w2t; cudaGetSymbolAddress((void**)&p_w2t, g_w2t);
    unsigned* p_wct; cudaGetSymbolAddress((void**)&p_wct, g_wct);
    float* p_bc;   cudaGetSymbolAddress((void**)&p_bc,  g_bc);

    const int EW = 256;
    int nNC = N_NODES * C;
    dim3 gemmGridH(2, (N_NODES + 127) / 128);   // N = 256
    dim3 gemmGridC(1, (N_NODES + 127) / 128);   // N = 128

    // --- BN(x) -> h  (g_sum/g_sumsq arrive zeroed; finalize re-zeroes) ---
    colstats<<<512, C>>>(x, N_NODES, C);
    finalize_stats<<<1, C>>>(C, N_NODES, bn_g, bn_b);
    bn_relu4<<<(nNC / 4 + EW - 1) / EW, EW>>>(x, p_h, nNC / 4, C / 4 - 1);

    // --- weight prep: single rounding launch + combined layer3/encoder ---
    round_w12<<<192, EW>>>(W1, W2);
    build_wct<<<384, 128>>>(W3, We);
    build_bc<<<1, 128>>>(b3, We, be);

    // --- build dst-CSR (counting sort; g_cnt arrives zeroed) ---
    hist<<<(N_EDGES + EW - 1) / EW, EW>>>(ei);
    scan_sums<<<NSCAN, SCAN_B>>>();
    scan_bsum<<<1, 128>>>();
    scan_final<<<NSCAN, SCAN_B>>>();
    scatter<<<(N_EDGES + EW - 1) / EW, EW>>>(ei);

    // --- softmax aggregation + root add (warp per node) ---
    agg_kernel<<<N_NODES / 8, 256>>>(p_h, p_min);

    // --- MLP layer 1: y0 = mlp_in @ W1 + b1 (stats fused) ---
    gemm_tc<false, true><<<gemmGridH, 256>>>(
        p_min, C, nullptr, 0, C, p_w1t, b1, p_y0, N_NODES, H, C);
    finalize_stats<<<1, H>>>(H, N_NODES, g1, be1);

    // --- MLP layer 2: y1 = relu(BN(y0)) @ W2 + b2 (pre + stats fused) ---
    gemm_tc<true, true><<<gemmGridH, 256>>>(
        p_y0, H, nullptr, 0, H, p_w2t, b2, p_y1, N_NODES, H, H);
    finalize_stats<<<1, H>>>(H, N_NODES, g2, be2);

    // --- fused layer3+encoder: out = [relu(BN(y1)) | x] @ Wc + bc ---
    gemm_tc<true, false><<<gemmGridC, 256>>>(
        p_y1, H, x, C, H, p_wct, p_bc, out, N_NODES, C, H + C);
}